// round 5
// baseline (speedup 1.0000x reference)
#include <cuda_runtime.h>

#define N_NODES 50000
#define N_EDGES 800000
#define D 128
#define NBATCH 64
#define ROWS_PER_BLOCK 8          // warps per block in k_agg

// ---------------- device scratch (allocation-free) ----------------
__device__ int   g_deg[N_NODES];        // per-dst degree
__device__ int   g_rowstart[N_NODES+1]; // CSR row offsets
__device__ int   g_cursor[N_NODES];     // fill cursors (copy of rowstart)
__device__ int   g_csr[N_EDGES];        // src indices grouped by dst
__device__ float g_S[NBATCH * D];       // per-batch sum of relu'd rows
__device__ float g_cnt[NBATCH];         // per-batch node count

// ---------------------------------------------------------------------------
// 1) zero degree + pooling accumulators
// ---------------------------------------------------------------------------
__global__ void k_setup() {
    int i = blockIdx.x * blockDim.x + threadIdx.x;
    if (i < N_NODES)    g_deg[i] = 0;
    if (i < NBATCH * D) g_S[i] = 0.0f;
    if (i < NBATCH)     g_cnt[i] = 0.0f;
}

// ---------------------------------------------------------------------------
// 2) histogram of dst
// ---------------------------------------------------------------------------
__global__ void k_hist(const int* __restrict__ ei) {
    int e = blockIdx.x * blockDim.x + threadIdx.x;
    if (e < N_EDGES) atomicAdd(&g_deg[ei[N_EDGES + e]], 1);
}

// ---------------------------------------------------------------------------
// 3) exclusive scan of g_deg -> g_rowstart (+ cursor copy). One 1024-thr block.
// ---------------------------------------------------------------------------
__global__ void k_scan() {
    __shared__ int sums[1024];
    const int CHUNK = (N_NODES + 1023) / 1024;   // 49
    int t = threadIdx.x;
    int beg = t * CHUNK;
    int end = beg + CHUNK; if (end > N_NODES) end = N_NODES;

    int s = 0;
    for (int i = beg; i < end; i++) s += g_deg[i];
    sums[t] = s;
    __syncthreads();
    // Hillis-Steele inclusive scan
    for (int off = 1; off < 1024; off <<= 1) {
        int v = (t >= off) ? sums[t - off] : 0;
        __syncthreads();
        sums[t] += v;
        __syncthreads();
    }
    int run = (t == 0) ? 0 : sums[t - 1];
    for (int i = beg; i < end; i++) {
        g_rowstart[i] = run;
        g_cursor[i]   = run;
        run += g_deg[i];
    }
    if (t == 0) g_rowstart[N_NODES] = N_EDGES;
}

// ---------------------------------------------------------------------------
// 4) permute: csr[pos[dst]++] = src
// ---------------------------------------------------------------------------
__global__ void k_fill(const int* __restrict__ ei) {
    int e = blockIdx.x * blockDim.x + threadIdx.x;
    if (e >= N_EDGES) return;
    int src = ei[e];
    int dst = ei[N_EDGES + e];
    int p = atomicAdd(&g_cursor[dst], 1);
    g_csr[p] = src;
}

// ---------------------------------------------------------------------------
// 5) fused: out[r] = relu((1+eps)x[r] + sum_{s in N(r)} x[s]),
//    plus per-batch pooled row-sums (batch is sorted by node index).
//    One warp per dst row; 8 rows per block.
// ---------------------------------------------------------------------------
__global__ void __launch_bounds__(256) k_agg(const float* __restrict__ x,
                      const float* __restrict__ eps,
                      const int* __restrict__ batch,
                      float* __restrict__ out) {
    __shared__ float sb[ROWS_PER_BLOCK * D];   // slot accumulators
    __shared__ float scnt[ROWS_PER_BLOCK];
    __shared__ int   sb0;

    int tid  = threadIdx.x;
    int warp = tid >> 5;
    int lane = tid & 31;
    int row  = blockIdx.x * ROWS_PER_BLOCK + warp;   // grid sized exactly

    // init smem
    #pragma unroll
    for (int k = 0; k < (ROWS_PER_BLOCK * D) / 256; k++)
        sb[tid + k * 256] = 0.0f;
    if (tid < ROWS_PER_BLOCK) scnt[tid] = 0.0f;
    if (tid == 0) sb0 = batch[blockIdx.x * ROWS_PER_BLOCK];
    __syncthreads();

    const float4* x4 = reinterpret_cast<const float4*>(x);
    float scale = 1.0f + eps[0];

    float4 xr = x4[(size_t)row * 32 + lane];
    float4 acc;
    acc.x = xr.x * scale; acc.y = xr.y * scale;
    acc.z = xr.z * scale; acc.w = xr.w * scale;

    int s0 = g_rowstart[row];
    int s1 = g_rowstart[row + 1];
    for (int base = s0; base < s1; base += 32) {
        int n = s1 - base; if (n > 32) n = 32;
        int idx = (base + lane < s1) ? g_csr[base + lane] : 0;
        #pragma unroll 4
        for (int j = 0; j < n; j++) {
            int s = __shfl_sync(0xffffffffu, idx, j);
            float4 v = x4[(size_t)s * 32 + lane];
            acc.x += v.x; acc.y += v.y; acc.z += v.z; acc.w += v.w;
        }
    }

    acc.x = fmaxf(acc.x, 0.0f); acc.y = fmaxf(acc.y, 0.0f);
    acc.z = fmaxf(acc.z, 0.0f); acc.w = fmaxf(acc.w, 0.0f);
    reinterpret_cast<float4*>(out)[(size_t)row * 32 + lane] = acc;

    // pooling: slot = batch[row] - first batch id in block (0..7, sorted)
    int b = batch[row];
    int slot = b - sb0;
    float* sp = &sb[slot * D + lane * 4];
    atomicAdd(sp + 0, acc.x);
    atomicAdd(sp + 1, acc.y);
    atomicAdd(sp + 2, acc.z);
    atomicAdd(sp + 3, acc.w);
    if (lane == 0) atomicAdd(&scnt[slot], 1.0f);
    __syncthreads();

    // flush used slots: warp w handles slot w
    int bmax = batch[blockIdx.x * ROWS_PER_BLOCK + (ROWS_PER_BLOCK - 1)];
    if (warp <= bmax - sb0) {
        float4 v = *reinterpret_cast<float4*>(&sb[warp * D + lane * 4]);
        float* p = &g_S[(sb0 + warp) * D + lane * 4];
        asm volatile("red.global.add.v4.f32 [%0], {%1, %2, %3, %4};"
                     :: "l"(p), "f"(v.x), "f"(v.y), "f"(v.z), "f"(v.w)
                     : "memory");
        if (lane == 0) atomicAdd(&g_cnt[sb0 + warp], scnt[warp]);
    }
}

// ---------------------------------------------------------------------------
// 6) pooled2[b] = S[b] @ W + cnt[b] * bias   (tiny; 4 independent FMA chains)
// ---------------------------------------------------------------------------
__global__ void k_pool(const float* __restrict__ W,
                       const float* __restrict__ bias,
                       float* __restrict__ out2) {
    int b = blockIdx.x;     // 0..63
    int j = threadIdx.x;    // 0..127
    __shared__ float s[D];
    s[j] = g_S[b * D + j];
    __syncthreads();

    float a0 = 0.f, a1 = 0.f, a2 = 0.f, a3 = 0.f;
    #pragma unroll
    for (int k = 0; k < D; k += 4) {
        a0 = fmaf(s[k + 0], __ldg(&W[(k + 0) * D + j]), a0);
        a1 = fmaf(s[k + 1], __ldg(&W[(k + 1) * D + j]), a1);
        a2 = fmaf(s[k + 2], __ldg(&W[(k + 2) * D + j]), a2);
        a3 = fmaf(s[k + 3], __ldg(&W[(k + 3) * D + j]), a3);
    }
    out2[b * D + j] = g_cnt[b] * bias[j] + ((a0 + a1) + (a2 + a3));
}

// ---------------------------------------------------------------------------
// launch
// ---------------------------------------------------------------------------
extern "C" void kernel_launch(void* const* d_in, const int* in_sizes, int n_in,
                              void* d_out, int out_size) {
    const float* x     = (const float*)d_in[0];
    const float* eps   = (const float*)d_in[1];
    const float* Wp    = (const float*)d_in[2];
    const float* bp    = (const float*)d_in[3];
    const int*   ei    = (const int*)d_in[4];
    const int*   batch = (const int*)d_in[5];

    float* out  = (float*)d_out;
    float* out2 = out + (size_t)N_NODES * D;

    k_setup<<<(N_NODES + 255) / 256, 256>>>();
    k_hist <<<(N_EDGES + 255) / 256, 256>>>(ei);
    k_scan <<<1, 1024>>>();
    k_fill <<<(N_EDGES + 255) / 256, 256>>>(ei);
    k_agg  <<<N_NODES / ROWS_PER_BLOCK, 256>>>(x, eps, batch, out);
    k_pool <<<NBATCH, 128>>>(Wp, bp, out2);
}

// round 6
// speedup vs baseline: 1.4308x; 1.4308x over previous
#include <cuda_runtime.h>

#define N_NODES 50000
#define N_EDGES 800000
#define D 128
#define NBATCH 64

// Device scratch (allocation-free). Zero-initialized at module load; every
// kernel_launch leaves them zeroed again (self-restoring), so no init kernel.
__device__ float g_agg[N_NODES * D];   // neighbor sums (zeroed by k_epilogue)
__device__ float g_S[NBATCH * D];      // per-batch pooled sums (zeroed by k_pool)
__device__ float g_cnt[NBATCH];        // per-batch node counts (zeroed by k_pool)

// ---------------------------------------------------------------------------
// 1) edge scatter: one warp per edge, lane = one float4 column chunk.
//    agg[dst] += x[src]  via vector L2 reduction. x and g_agg are L2-resident.
// ---------------------------------------------------------------------------
__global__ void k_edges(const float* __restrict__ x,
                        const int* __restrict__ ei) {
    int warp = (blockIdx.x * blockDim.x + threadIdx.x) >> 5;
    int lane = threadIdx.x & 31;
    if (warp >= N_EDGES) return;
    int src = __ldg(&ei[warp]);
    int dst = __ldg(&ei[N_EDGES + warp]);

    float4 v = reinterpret_cast<const float4*>(x)[(size_t)src * 32 + lane];

    float* p = g_agg + (size_t)dst * D + lane * 4;
    asm volatile("red.global.add.v4.f32 [%0], {%1, %2, %3, %4};"
                 :: "l"(p), "f"(v.x), "f"(v.y), "f"(v.z), "f"(v.w)
                 : "memory");
}

// ---------------------------------------------------------------------------
// 2) epilogue: out = relu(scale*x + agg), re-zero agg, and per-batch pooled
//    row-sums with run-length compression (batch is sorted).
//    One warp per 16 consecutive rows; lane = one float4.
// ---------------------------------------------------------------------------
#define EPI_ROWS 16

__global__ void __launch_bounds__(256) k_epilogue(const float* __restrict__ x,
                                                  const float* __restrict__ eps,
                                                  const int* __restrict__ batch,
                                                  float* __restrict__ out) {
    int warp = (blockIdx.x * blockDim.x + threadIdx.x) >> 5;
    int lane = threadIdx.x & 31;
    int r0 = warp * EPI_ROWS;
    if (r0 >= N_NODES) return;
    int r1 = r0 + EPI_ROWS; if (r1 > N_NODES) r1 = N_NODES;

    float scale = 1.0f + eps[0];
    float4* agg4 = reinterpret_cast<float4*>(g_agg);
    const float4* x4 = reinterpret_cast<const float4*>(x);
    float4* out4 = reinterpret_cast<float4*>(out);
    const float4 zero4 = make_float4(0.f, 0.f, 0.f, 0.f);

    float4 acc = zero4;
    int cnt = 0;
    int cur = batch[r0];   // broadcast load

    for (int r = r0; r < r1; r++) {
        size_t idx = (size_t)r * 32 + lane;
        float4 a  = agg4[idx];
        float4 xv = x4[idx];
        float4 v;
        v.x = fmaxf(fmaf(xv.x, scale, a.x), 0.f);
        v.y = fmaxf(fmaf(xv.y, scale, a.y), 0.f);
        v.z = fmaxf(fmaf(xv.z, scale, a.z), 0.f);
        v.w = fmaxf(fmaf(xv.w, scale, a.w), 0.f);
        out4[idx] = v;
        agg4[idx] = zero4;                 // self-restore for next replay

        int b = batch[r];
        if (b != cur) {
            float* p = &g_S[cur * D + lane * 4];
            asm volatile("red.global.add.v4.f32 [%0], {%1, %2, %3, %4};"
                         :: "l"(p), "f"(acc.x), "f"(acc.y), "f"(acc.z), "f"(acc.w)
                         : "memory");
            if (lane == 0) atomicAdd(&g_cnt[cur], (float)cnt);
            cur = b; acc = zero4; cnt = 0;
        }
        acc.x += v.x; acc.y += v.y; acc.z += v.z; acc.w += v.w;
        cnt++;
    }
    {
        float* p = &g_S[cur * D + lane * 4];
        asm volatile("red.global.add.v4.f32 [%0], {%1, %2, %3, %4};"
                     :: "l"(p), "f"(acc.x), "f"(acc.y), "f"(acc.z), "f"(acc.w)
                     : "memory");
        if (lane == 0) atomicAdd(&g_cnt[cur], (float)cnt);
    }
}

// ---------------------------------------------------------------------------
// 3) pooled2[b] = S[b] @ W + cnt[b]*bias  (64x128x128). Reads then re-zeroes
//    g_S / g_cnt. 4 independent FMA chains, full unroll.
// ---------------------------------------------------------------------------
__global__ void k_pool(const float* __restrict__ W,
                       const float* __restrict__ bias,
                       float* __restrict__ out2) {
    int b = blockIdx.x;     // 0..63
    int j = threadIdx.x;    // 0..127
    __shared__ float s[D];
    __shared__ float cntf;
    s[j] = g_S[b * D + j];
    g_S[b * D + j] = 0.0f;                 // self-restore
    if (j == 0) { cntf = g_cnt[b]; g_cnt[b] = 0.0f; }
    __syncthreads();

    float a0 = 0.f, a1 = 0.f, a2 = 0.f, a3 = 0.f;
    #pragma unroll
    for (int k = 0; k < D; k += 4) {
        a0 = fmaf(s[k + 0], __ldg(&W[(k + 0) * D + j]), a0);
        a1 = fmaf(s[k + 1], __ldg(&W[(k + 1) * D + j]), a1);
        a2 = fmaf(s[k + 2], __ldg(&W[(k + 2) * D + j]), a2);
        a3 = fmaf(s[k + 3], __ldg(&W[(k + 3) * D + j]), a3);
    }
    out2[b * D + j] = cntf * bias[j] + ((a0 + a1) + (a2 + a3));
}

// ---------------------------------------------------------------------------
// launch: x, eps, W_pred, b_pred, edge_index, batch -> out | pooled2
// ---------------------------------------------------------------------------
extern "C" void kernel_launch(void* const* d_in, const int* in_sizes, int n_in,
                              void* d_out, int out_size) {
    const float* x     = (const float*)d_in[0];
    const float* eps   = (const float*)d_in[1];
    const float* Wp    = (const float*)d_in[2];
    const float* bp    = (const float*)d_in[3];
    const int*   ei    = (const int*)d_in[4];
    const int*   batch = (const int*)d_in[5];

    float* out  = (float*)d_out;
    float* out2 = out + (size_t)N_NODES * D;

    // edge scatter: one warp per edge
    {
        long long totalThreads = (long long)N_EDGES * 32;
        int blocks = (int)((totalThreads + 255) / 256);
        k_edges<<<blocks, 256>>>(x, ei);
    }

    // epilogue: relu + out + agg re-zero + batch partial sums
    {
        int warps = (N_NODES + EPI_ROWS - 1) / EPI_ROWS;     // 3125
        int blocks = (warps * 32 + 255) / 256;               // 391
        k_epilogue<<<blocks, 256>>>(x, eps, batch, out);
    }

    // tiny pooled GEMM
    k_pool<<<NBATCH, 128>>>(Wp, bp, out2);
}

// round 7
// speedup vs baseline: 1.5752x; 1.1009x over previous
#include <cuda_runtime.h>

#define N_NODES 50000
#define N_EDGES 800000
#define D 128
#define NBATCH 64
#define EPW 16                 // edges per warp in k_edges (800000 = 50000*16)

// Device scratch (allocation-free). Zero-initialized at module load; every
// kernel_launch leaves them zeroed again (self-restoring), so no init kernel.
__device__ float g_agg[N_NODES * D];   // neighbor sums (zeroed by k_epilogue)
__device__ float g_S[NBATCH * D];      // per-batch pooled sums (zeroed by k_pool)
__device__ float g_cnt[NBATCH];        // per-batch node counts (zeroed by k_pool)

// ---------------------------------------------------------------------------
// 1) edge scatter: one warp per 16 edges.
//    Lanes 0-15 load src indices, lanes 16-31 load dst indices (coalesced),
//    then 16 independent gather+reduce chains (high MLP, few warps).
// ---------------------------------------------------------------------------
__global__ void __launch_bounds__(256) k_edges(const float* __restrict__ x,
                                               const int* __restrict__ ei) {
    int warp = (blockIdx.x * blockDim.x + threadIdx.x) >> 5;
    int lane = threadIdx.x & 31;
    long long base = (long long)warp * EPW;
    if (base >= N_EDGES) return;

    // coalesced index fetch: 16 srcs (lanes 0-15), 16 dsts (lanes 16-31)
    int idx = (lane < EPW) ? __ldg(&ei[base + lane])
                           : __ldg(&ei[N_EDGES + base + (lane - EPW)]);

    const float4* x4 = reinterpret_cast<const float4*>(x);

    #pragma unroll
    for (int j = 0; j < EPW; j++) {
        int s = __shfl_sync(0xffffffffu, idx, j);
        int d = __shfl_sync(0xffffffffu, idx, EPW + j);
        float4 v = x4[(size_t)s * 32 + lane];
        float* p = g_agg + (size_t)d * D + lane * 4;
        asm volatile("red.global.add.v4.f32 [%0], {%1, %2, %3, %4};"
                     :: "l"(p), "f"(v.x), "f"(v.y), "f"(v.z), "f"(v.w)
                     : "memory");
    }
}

// ---------------------------------------------------------------------------
// 2) epilogue: out = relu(scale*x + agg), re-zero agg, and per-batch pooled
//    row-sums with run-length compression (batch is sorted).
//    One warp per 16 consecutive rows; lane = one float4.
// ---------------------------------------------------------------------------
#define EPI_ROWS 16

__global__ void __launch_bounds__(256) k_epilogue(const float* __restrict__ x,
                                                  const float* __restrict__ eps,
                                                  const int* __restrict__ batch,
                                                  float* __restrict__ out) {
    int warp = (blockIdx.x * blockDim.x + threadIdx.x) >> 5;
    int lane = threadIdx.x & 31;
    int r0 = warp * EPI_ROWS;
    if (r0 >= N_NODES) return;
    int r1 = r0 + EPI_ROWS; if (r1 > N_NODES) r1 = N_NODES;

    float scale = 1.0f + eps[0];
    float4* agg4 = reinterpret_cast<float4*>(g_agg);
    const float4* x4 = reinterpret_cast<const float4*>(x);
    float4* out4 = reinterpret_cast<float4*>(out);
    const float4 zero4 = make_float4(0.f, 0.f, 0.f, 0.f);

    float4 acc = zero4;
    int cnt = 0;
    int cur = batch[r0];   // broadcast load

    for (int r = r0; r < r1; r++) {
        size_t idx = (size_t)r * 32 + lane;
        float4 a  = agg4[idx];
        float4 xv = x4[idx];
        float4 v;
        v.x = fmaxf(fmaf(xv.x, scale, a.x), 0.f);
        v.y = fmaxf(fmaf(xv.y, scale, a.y), 0.f);
        v.z = fmaxf(fmaf(xv.z, scale, a.z), 0.f);
        v.w = fmaxf(fmaf(xv.w, scale, a.w), 0.f);
        out4[idx] = v;
        agg4[idx] = zero4;                 // self-restore for next replay

        int b = batch[r];
        if (b != cur) {
            float* p = &g_S[cur * D + lane * 4];
            asm volatile("red.global.add.v4.f32 [%0], {%1, %2, %3, %4};"
                         :: "l"(p), "f"(acc.x), "f"(acc.y), "f"(acc.z), "f"(acc.w)
                         : "memory");
            if (lane == 0) atomicAdd(&g_cnt[cur], (float)cnt);
            cur = b; acc = zero4; cnt = 0;
        }
        acc.x += v.x; acc.y += v.y; acc.z += v.z; acc.w += v.w;
        cnt++;
    }
    {
        float* p = &g_S[cur * D + lane * 4];
        asm volatile("red.global.add.v4.f32 [%0], {%1, %2, %3, %4};"
                     :: "l"(p), "f"(acc.x), "f"(acc.y), "f"(acc.z), "f"(acc.w)
                     : "memory");
        if (lane == 0) atomicAdd(&g_cnt[cur], (float)cnt);
    }
}

// ---------------------------------------------------------------------------
// 3) pooled2[b] = S[b] @ W + cnt[b]*bias  (64x128x128). Reads then re-zeroes
//    g_S / g_cnt. 4 independent FMA chains, full unroll.
// ---------------------------------------------------------------------------
__global__ void k_pool(const float* __restrict__ W,
                       const float* __restrict__ bias,
                       float* __restrict__ out2) {
    int b = blockIdx.x;     // 0..63
    int j = threadIdx.x;    // 0..127
    __shared__ float s[D];
    __shared__ float cntf;
    s[j] = g_S[b * D + j];
    g_S[b * D + j] = 0.0f;                 // self-restore
    if (j == 0) { cntf = g_cnt[b]; g_cnt[b] = 0.0f; }
    __syncthreads();

    float a0 = 0.f, a1 = 0.f, a2 = 0.f, a3 = 0.f;
    #pragma unroll
    for (int k = 0; k < D; k += 4) {
        a0 = fmaf(s[k + 0], __ldg(&W[(k + 0) * D + j]), a0);
        a1 = fmaf(s[k + 1], __ldg(&W[(k + 1) * D + j]), a1);
        a2 = fmaf(s[k + 2], __ldg(&W[(k + 2) * D + j]), a2);
        a3 = fmaf(s[k + 3], __ldg(&W[(k + 3) * D + j]), a3);
    }
    out2[b * D + j] = cntf * bias[j] + ((a0 + a1) + (a2 + a3));
}

// ---------------------------------------------------------------------------
// launch: x, eps, W_pred, b_pred, edge_index, batch -> out | pooled2
// ---------------------------------------------------------------------------
extern "C" void kernel_launch(void* const* d_in, const int* in_sizes, int n_in,
                              void* d_out, int out_size) {
    const float* x     = (const float*)d_in[0];
    const float* eps   = (const float*)d_in[1];
    const float* Wp    = (const float*)d_in[2];
    const float* bp    = (const float*)d_in[3];
    const int*   ei    = (const int*)d_in[4];
    const int*   batch = (const int*)d_in[5];

    float* out  = (float*)d_out;
    float* out2 = out + (size_t)N_NODES * D;

    // edge scatter: one warp per EPW edges
    {
        int warps = (N_EDGES + EPW - 1) / EPW;               // 50000
        int blocks = (warps * 32 + 255) / 256;               // 6250
        k_edges<<<blocks, 256>>>(x, ei);
    }

    // epilogue: relu + out + agg re-zero + batch partial sums
    {
        int warps = (N_NODES + EPI_ROWS - 1) / EPI_ROWS;     // 3125
        int blocks = (warps * 32 + 255) / 256;               // 391
        k_epilogue<<<blocks, 256>>>(x, eps, batch, out);
    }

    // tiny pooled GEMM
    k_pool<<<NBATCH, 128>>>(Wp, bp, out2);
}